// round 12
// baseline (speedup 1.0000x reference)
#include <cuda_runtime.h>
#include <cuda_bf16.h>

#define B_ 4
#define T_ 128
#define N_ 512
#define D_ 32
#define JN_ 16384       // (B*T)*D
#define EMB_ 10

typedef unsigned long long u64;
typedef unsigned int u32;

// ---------------- f32x2 packed helpers (sm_103a FFMA2) -----------------------
__device__ __forceinline__ u64 pack2(float lo, float hi) {
    u64 r; asm("mov.b64 %0, {%1, %2};" : "=l"(r) : "f"(lo), "f"(hi)); return r;
}
__device__ __forceinline__ void unpack2(u64 v, float& lo, float& hi) {
    asm("mov.b64 {%0, %1}, %2;" : "=f"(lo), "=f"(hi) : "l"(v));
}
__device__ __forceinline__ u64 fma2(u64 a, u64 b, u64 c) {
    u64 d; asm("fma.rn.f32x2 %0, %1, %2, %3;" : "=l"(d) : "l"(a), "l"(b), "l"(c)); return d;
}
__device__ __forceinline__ u64 mul2(u64 a, u64 b) {
    u64 d; asm("mul.rn.f32x2 %0, %1, %2;" : "=l"(d) : "l"(a), "l"(b)); return d;
}
__device__ __forceinline__ u64 add2(u64 a, u64 b) {
    u64 d; asm("add.rn.f32x2 %0, %1, %2;" : "=l"(d) : "l"(a), "l"(b)); return d;
}
__device__ __forceinline__ u64 relu2(u64 v) {
    float a, b; unpack2(v, a, b);
    return pack2(fmaxf(a, 0.f), fmaxf(b, 0.f));
}
__device__ __forceinline__ u32 smem_u32(const void* p) {
    u32 a;
    asm("{ .reg .u64 t; cvta.to.shared.u64 t, %1; cvt.u32.u64 %0, t; }"
        : "=r"(a) : "l"(p));
    return a;
}
// ---------------- mma.sync helpers (sm_80+ path, HMMA on sm_103) ------------
__device__ __forceinline__ void ldmx4(u32& r0, u32& r1, u32& r2, u32& r3, u32 a) {
    asm volatile("ldmatrix.sync.aligned.m8n8.x4.shared.b16 {%0,%1,%2,%3}, [%4];"
                 : "=r"(r0), "=r"(r1), "=r"(r2), "=r"(r3) : "r"(a));
}
__device__ __forceinline__ void ldmx4t(u32& r0, u32& r1, u32& r2, u32& r3, u32 a) {
    asm volatile("ldmatrix.sync.aligned.m8n8.x4.trans.shared.b16 {%0,%1,%2,%3}, [%4];"
                 : "=r"(r0), "=r"(r1), "=r"(r2), "=r"(r3) : "r"(a));
}
__device__ __forceinline__ void mma16816(float* c, const u32* a, const u32* b) {
    asm volatile(
        "mma.sync.aligned.m16n8k16.row.col.f32.bf16.bf16.f32 "
        "{%0,%1,%2,%3}, {%4,%5,%6,%7}, {%8,%9}, {%0,%1,%2,%3};"
        : "+f"(c[0]), "+f"(c[1]), "+f"(c[2]), "+f"(c[3])
        : "r"(a[0]), "r"(a[1]), "r"(a[2]), "r"(a[3]), "r"(b[0]), "r"(b[1]));
}
__device__ __forceinline__ void cpa16(u32 dst, const void* src) {
    asm volatile("cp.async.cg.shared.global [%0], [%1], 16;"
                 :: "r"(dst), "l"(src));
}

// ---------------- scratch (device globals; no allocations allowed) ----------
__device__ float g_buf0[N_ * JN_];       // layout (n, bt, c), bt = b*T+t
__device__ float g_buf1[N_ * JN_];
__device__ float g_xg[2 * N_ * JN_];     // aggregated supports k=1,2
__device__ float g_W[3 * N_ * 3 * D_ * D_];   // per-layer per-node (k,c,o)
__device__ float g_bias[3 * N_ * D_];
// bf16 2-term splits
__device__ __nv_bfloat16 g_A0[1024 * 512], g_A1[1024 * 512];
__device__ __nv_bfloat16 g_B0[N_ * JN_], g_B1[N_ * JN_];

// ---------------- transpose x (bt,n,c) -> (n,bt,c), fused bf16 split --------
__global__ void k_transpose(const float* __restrict__ x) {
    int n = blockIdx.x, bt0 = blockIdx.y * 64, tid = threadIdx.x;
#pragma unroll
    for (int j = 0; j < 8; j++) {
        int idx = j * 256 + tid;
        int r = idx >> 5, c = idx & 31;
        float v = x[(bt0 + r) * (N_ * D_) + n * D_ + c];
        int di = n * JN_ + (bt0 + r) * D_ + c;
        g_buf0[di] = v;
        __nv_bfloat16 h = __float2bfloat16_rn(v);
        g_B0[di] = h;
        g_B1[di] = __float2bfloat16_rn(v - __bfloat162float(h));
    }
}

// ---------------- S2 = 2*adj@adj - I, fused bf16 split ----------------------
__global__ void k_s2(const float* __restrict__ A) {
    __shared__ float As[32][33], Bs[32][33];
    int by = blockIdx.y, bx = blockIdx.x, tid = threadIdx.x;
    int ty = tid >> 5, tx = tid & 31;
    float acc[4] = {0.f, 0.f, 0.f, 0.f};
    for (int m0 = 0; m0 < N_; m0 += 32) {
#pragma unroll
        for (int i = 0; i < 4; i++) {
            int r = ty + i * 8;
            As[r][tx] = A[(by * 32 + r) * N_ + m0 + tx];
            Bs[r][tx] = A[(m0 + r) * N_ + bx * 32 + tx];
        }
        __syncthreads();
#pragma unroll
        for (int m = 0; m < 32; m++) {
            float b = Bs[m][tx];
#pragma unroll
            for (int i = 0; i < 4; i++) acc[i] += As[ty + i * 8][m] * b;
        }
        __syncthreads();
    }
#pragma unroll
    for (int i = 0; i < 4; i++) {
        int r = by * 32 + ty + i * 8, c = bx * 32 + tx;
        float v = 2.f * acc[i] - (r == c ? 1.f : 0.f);
        __nv_bfloat16 h = __float2bfloat16_rn(v);
        g_A0[(512 + r) * 512 + c] = h;
        g_A1[(512 + r) * 512 + c] = __float2bfloat16_rn(v - __bfloat162float(h));
    }
}

// ---------------- per-node GCN weights --------------------------------------
__global__ void k_wn(const float* __restrict__ E, const float* __restrict__ gw,
                     const float* __restrict__ gb) {
    int n = blockIdx.x, L = blockIdx.y, tid = threadIdx.x;
    float Er[EMB_];
#pragma unroll
    for (int e = 0; e < EMB_; e++) Er[e] = E[n * EMB_ + e];
    const float* g0 = gw + L * (EMB_ * 3072);
    float* wout = g_W + (L * N_ + n) * 3072;
    for (int idx = tid; idx < 3072; idx += 256) {
        float a = 0.f;
#pragma unroll
        for (int e = 0; e < EMB_; e++) a += Er[e] * g0[e * 3072 + idx];
        wout[idx] = a;
    }
    if (tid < 32) {
        const float* b0 = gb + L * (EMB_ * 32);
        float a = 0.f;
#pragma unroll
        for (int e = 0; e < EMB_; e++) a += Er[e] * b0[e * 32 + tid];
        g_bias[(L * N_ + n) * 32 + tid] = a;
    }
}

// ---------------- bf16 2-term split of adj rows (S2 handled by k_s2) --------
__global__ void k_prep(const float* __restrict__ adj) {
    int r = blockIdx.x, tid = threadIdx.x;
    const float* src = &adj[r * 512];
    for (int c = tid; c < 512; c += 256) {
        float v = src[c];
        __nv_bfloat16 h = __float2bfloat16_rn(v);
        g_A0[r * 512 + c] = h;
        g_A1[r * 512 + c] = __float2bfloat16_rn(v - __bfloat162float(h));
    }
}

// ---------------- tensor-core aggregation GEMM via mma.sync -----------------
#define AGG_STAGE 37888
#define AGG_SMEM (2 * AGG_STAGE)    // 75776
__global__ void __launch_bounds__(256) k_aggM() {
    extern __shared__ char smdyn[];
    u32 sbase = smem_u32(smdyn);
    int tid = threadIdx.x, lane = tid & 31, wid = tid >> 5;
    int j0 = blockIdx.x * 128, i0 = blockIdx.y * 128;
    int wm = wid >> 2, wj = wid & 3;
    int lr = lane & 15, lh = lane >> 4;
    float acc[4][4][4];
#pragma unroll
    for (int mt = 0; mt < 4; mt++)
#pragma unroll
        for (int nt = 0; nt < 4; nt++)
#pragma unroll
            for (int q = 0; q < 4; q++) acc[mt][nt][q] = 0.f;

    auto loadStage = [&](int ch, int st) {
        u32 sb = sbase + st * AGG_STAGE;
        int k0 = ch * 32;
#pragma unroll
        for (int it = 0; it < 2; it++) {
            int idx = it * 256 + tid;
            int row = idx >> 2, c16 = idx & 3;
            cpa16(sb + row * 80 + c16 * 16,
                  &g_A0[(i0 + row) * 512 + k0 + c16 * 8]);
            cpa16(sb + 10240 + row * 80 + c16 * 16,
                  &g_A1[(i0 + row) * 512 + k0 + c16 * 8]);
        }
#pragma unroll
        for (int it = 0; it < 2; it++) {
            int idx = it * 256 + tid;
            int k = idx >> 4, c = idx & 15;
            cpa16(sb + 20480 + k * 272 + c * 16,
                  &g_B0[(size_t)(k0 + k) * JN_ + j0 + c * 8]);
            cpa16(sb + 29184 + k * 272 + c * 16,
                  &g_B1[(size_t)(k0 + k) * JN_ + j0 + c * 8]);
        }
        asm volatile("cp.async.commit_group;" ::: "memory");
    };

    loadStage(0, 0);
    for (int ch = 0; ch < 16; ch++) {
        if (ch + 1 < 16) {
            loadStage(ch + 1, (ch + 1) & 1);
            asm volatile("cp.async.wait_group 1;" ::: "memory");
        } else {
            asm volatile("cp.async.wait_group 0;" ::: "memory");
        }
        __syncthreads();
        u32 sb = sbase + (ch & 1) * AGG_STAGE;
        u32 aH = sb, aM = sb + 10240, bH = sb + 20480, bM = sb + 29184;
#pragma unroll
        for (int s2 = 0; s2 < 32; s2 += 16) {
            u32 bh[4][2], bm[4][2];
#pragma unroll
            for (int half = 0; half < 2; half++) {
                u32 boff = (u32)((s2 + lr) * 272 +
                                 (wj * 32 + half * 16 + lh * 8) * 2);
                u32 r0, r1, r2, r3;
                ldmx4t(r0, r1, r2, r3, bH + boff);
                bh[half * 2][0] = r0; bh[half * 2][1] = r1;
                bh[half * 2 + 1][0] = r2; bh[half * 2 + 1][1] = r3;
                ldmx4t(r0, r1, r2, r3, bM + boff);
                bm[half * 2][0] = r0; bm[half * 2][1] = r1;
                bm[half * 2 + 1][0] = r2; bm[half * 2 + 1][1] = r3;
            }
#pragma unroll
            for (int mt = 0; mt < 4; mt++) {
                u32 aoff = (u32)((wm * 64 + mt * 16 + lr) * 80 +
                                 (s2 + lh * 8) * 2);
                u32 ah[4], am[4];
                ldmx4(ah[0], ah[1], ah[2], ah[3], aH + aoff);
                ldmx4(am[0], am[1], am[2], am[3], aM + aoff);
#pragma unroll
                for (int nt = 0; nt < 4; nt++) {
                    mma16816(acc[mt][nt], ah, bh[nt]);
                    mma16816(acc[mt][nt], ah, bm[nt]);
                    mma16816(acc[mt][nt], am, bh[nt]);
                }
            }
        }
        __syncthreads();
    }
    int rbase = i0 + wm * 64 + (lane >> 2);
    int cbase = j0 + wj * 32 + 2 * (lane & 3);
#pragma unroll
    for (int mt = 0; mt < 4; mt++)
#pragma unroll
        for (int nt = 0; nt < 4; nt++) {
            size_t base = (size_t)(rbase + mt * 16) * JN_ + cbase + nt * 8;
            *(float2*)&g_xg[base] = make_float2(acc[mt][nt][0], acc[mt][nt][1]);
            *(float2*)&g_xg[base + 8 * JN_] =
                make_float2(acc[mt][nt][2], acc[mt][nt][3]);
        }
}

// ---------------- combine: 256 thr, 128 bt rows/block, fused split ----------
#define CMB_SMEM (12288 + 96 * 132 * 4)   // Ws + Xin = 62976
__global__ void __launch_bounds__(256) k_combine(int inSel, int L, int doSplit) {
    extern __shared__ char csm[];
    float* Ws = (float*)csm;
    float (*Xin)[132] = (float(*)[132])(csm + 12288);
    __shared__ float bs[32];
    const float* Hin = inSel ? g_buf1 : g_buf0;
    float* Hout = inSel ? g_buf0 : g_buf1;
    int n = blockIdx.x, bt0 = blockIdx.y * 128, tid = threadIdx.x;
    const float* Wl = g_W + (L * N_ + n) * 3072;
    for (int q = tid; q < 3072; q += 256) Ws[q] = Wl[q];
    if (tid < 32) bs[tid] = g_bias[(L * N_ + n) * 32 + tid];
    const float* s0 = Hin + n * JN_ + bt0 * D_;
    const float* s1 = g_xg + n * JN_ + bt0 * D_;
    const float* s2 = g_xg + (N_ + n) * JN_ + bt0 * D_;
#pragma unroll
    for (int q = tid; q < 4096; q += 256) {
        int r = q >> 5, c = q & 31;
        Xin[c][r] = s0[q];
        Xin[32 + c][r] = s1[q];
        Xin[64 + c][r] = s2[q];
    }
    __syncthreads();
    int to = tid & 7, tb = tid >> 3;   // o-cols to*4..+3; bt rows tb*4..+3 (tb 0..31)
    float acc[4][4];
#pragma unroll
    for (int i = 0; i < 4; i++)
#pragma unroll
        for (int j = 0; j < 4; j++) acc[i][j] = 0.f;
    for (int kc = 0; kc < 96; kc++) {
        float4 xv = *(const float4*)&Xin[kc][tb * 4];
        float4 wv = *(const float4*)&Ws[kc * 32 + to * 4];
        acc[0][0] += xv.x * wv.x; acc[0][1] += xv.x * wv.y;
        acc[0][2] += xv.x * wv.z; acc[0][3] += xv.x * wv.w;
        acc[1][0] += xv.y * wv.x; acc[1][1] += xv.y * wv.y;
        acc[1][2] += xv.y * wv.z; acc[1][3] += xv.y * wv.w;
        acc[2][0] += xv.z * wv.x; acc[2][1] += xv.z * wv.y;
        acc[2][2] += xv.z * wv.z; acc[2][3] += xv.z * wv.w;
        acc[3][0] += xv.w * wv.x; acc[3][1] += xv.w * wv.y;
        acc[3][2] += xv.w * wv.z; acc[3][3] += xv.w * wv.w;
    }
    float4 bv = *(const float4*)&bs[to * 4];
#pragma unroll
    for (int i = 0; i < 4; i++) {
        int bt = bt0 + tb * 4 + i;
        float o0 = acc[i][0] + bv.x, o1 = acc[i][1] + bv.y;
        float o2 = acc[i][2] + bv.z, o3 = acc[i][3] + bv.w;
        int di = n * JN_ + bt * D_ + to * 4;
        *(float4*)&Hout[di] = make_float4(o0, o1, o2, o3);
        if (doSplit) {
            float vv[4] = {o0, o1, o2, o3};
            unsigned short hs[4], ms[4];
#pragma unroll
            for (int q = 0; q < 4; q++) {
                __nv_bfloat16 h = __float2bfloat16_rn(vv[q]);
                hs[q] = __bfloat16_as_ushort(h);
                ms[q] = __bfloat16_as_ushort(
                    __float2bfloat16_rn(vv[q] - __bfloat162float(h)));
            }
            *(uint2*)&g_B0[di] = make_uint2((u32)hs[0] | ((u32)hs[1] << 16),
                                            (u32)hs[2] | ((u32)hs[3] << 16));
            *(uint2*)&g_B1[di] = make_uint2((u32)ms[0] | ((u32)ms[1] << 16),
                                            (u32)ms[2] | ((u32)ms[3] << 16));
        }
    }
}

// ---------------- fused TCN: 256 thr, o-split halves, 2 seqs/block ----------
#define TCN_SMEM 90880
__global__ void __launch_bounds__(256)
k_tcn(const float* __restrict__ w1, const float* __restrict__ b1,
      const float* __restrict__ w2, const float* __restrict__ b2, int sel) {
    extern __shared__ char dsm[];
    ulonglong2* e01 = (ulonglong2*)dsm;                 // [1024] {dup w0, dup w1}
    u64* wd2 = (u64*)(dsm + 16384);                     // [1024] dup w2
    u64* bb  = (u64*)(dsm + 16384 + 8192);              // [32] dup bias
    u64 (*y0)[129] = (u64(*)[129])(dsm + 24832);
    u64 (*y1)[129] = (u64(*)[129])(dsm + 24832 + 33024);

    float* base = sel ? g_buf1 : g_buf0;
    float* seqA = base + (2 * blockIdx.x) * 4096;
    float* seqB = seqA + 4096;
    int tid = threadIdx.x;
    int t = tid & 127, ob = (tid >> 7) * 16;   // o-range [ob, ob+16)

    for (int idx = tid; idx < 4096; idx += 256) {
        int c = idx & 31, tt = idx >> 5;
        y0[c][tt] = pack2(seqA[idx], seqB[idx]);
    }
    for (int blk = 0; blk < 3; blk++) {
        int dil = 1 << blk;
        __syncthreads();
        const float* ws = w1 + blk * 3072;
        for (int q = tid; q < 1024; q += 256) {
            float a = ws[q * 3], b = ws[q * 3 + 1], c = ws[q * 3 + 2];
            e01[q] = make_ulonglong2(pack2(a, a), pack2(b, b));
            wd2[q] = pack2(c, c);
        }
        if (tid < 32) { float v = b1[blk * 32 + tid]; bb[tid] = pack2(v, v); }
        __syncthreads();
        u64 acc[16];
#pragma unroll
        for (int o = 0; o < 16; o++) acc[o] = bb[ob + o];
        for (int c = 0; c < 32; c++) {
            u64 i0 = (t >= 2 * dil) ? y0[c][t - 2 * dil] : 0ULL;
            u64 i1 = (t >= dil) ? y0[c][t - dil] : 0ULL;
            u64 i2 = y0[c][t];
#pragma unroll
            for (int o = 0; o < 16; o++) {
                ulonglong2 w01 = e01[(ob + o) * 32 + c];
                acc[o] = fma2(w01.x, i0, acc[o]);
                acc[o] = fma2(w01.y, i1, acc[o]);
                acc[o] = fma2(wd2[(ob + o) * 32 + c], i2, acc[o]);
            }
        }
#pragma unroll
        for (int o = 0; o < 16; o++) y1[ob + o][t] = relu2(acc[o]);
        __syncthreads();
        const float* ws2 = w2 + blk * 3072;
        for (int q = tid; q < 1024; q += 256) {
            float a = ws2[q * 3], b = ws2[q * 3 + 1], c = ws2[q * 3 + 2];
            e01[q] = make_ulonglong2(pack2(a, a), pack2(b, b));
            wd2[q] = pack2(c, c);
        }
        if (tid < 32) { float v = b2[blk * 32 + tid]; bb[tid] = pack2(v, v); }
        __syncthreads();
#pragma unroll
        for (int o = 0; o < 16; o++) acc[o] = bb[ob + o];
        for (int c = 0; c < 32; c++) {
            u64 i0 = (t >= 2 * dil) ? y1[c][t - 2 * dil] : 0ULL;
            u64 i1 = (t >= dil) ? y1[c][t - dil] : 0ULL;
            u64 i2 = y1[c][t];
#pragma unroll
            for (int o = 0; o < 16; o++) {
                ulonglong2 w01 = e01[(ob + o) * 32 + c];
                acc[o] = fma2(w01.x, i0, acc[o]);
                acc[o] = fma2(w01.y, i1, acc[o]);
                acc[o] = fma2(wd2[(ob + o) * 32 + c], i2, acc[o]);
            }
        }
        // residual + relu; each (o,t) owned by exactly one thread
#pragma unroll
        for (int o = 0; o < 16; o++)
            y0[ob + o][t] = relu2(add2(relu2(acc[o]), y0[ob + o][t]));
    }
    __syncthreads();
    for (int idx = tid; idx < 4096; idx += 256) {
        int c = idx & 31, tt = idx >> 5;
        float lo, hi; unpack2(y0[c][tt], lo, hi);
        seqA[idx] = lo; seqB[idx] = hi;
    }
}

// ---------------- merged 2-layer temporal attention + layernorm -------------
__global__ void __launch_bounds__(128)
k_attn2(const float* __restrict__ wq, const float* __restrict__ wk,
        const float* __restrict__ wv, const float* __restrict__ wo,
        const float* __restrict__ gga, const float* __restrict__ bba,
        int sel, float* __restrict__ finalOut) {
    __shared__ ulonglong2 Kp[128][8];
    __shared__ ulonglong2 Vp[128][8];
    __shared__ ulonglong2 Wq2[32][8];   // reused for Wo
    __shared__ ulonglong2 Wk2[32][8];
    __shared__ ulonglong2 Wv2[32][8];
    __shared__ float gs[2][32], bs2[2][32];
    const float* seq = (sel ? g_buf1 : g_buf0) + blockIdx.x * 4096;
    int t = threadIdx.x;
    u64* Wq2u = (u64*)Wq2; u64* Wk2u = (u64*)Wk2; u64* Wv2u = (u64*)Wv2;

    if (t < 64) {
        int L = t >> 5, o = t & 31;
        gs[L][o] = gga[L * 32 + o];
        bs2[L][o] = bba[L * 32 + o];
    }
    float hrow[32];
#pragma unroll
    for (int o4 = 0; o4 < 8; o4++)
        *(float4*)&hrow[o4 * 4] = *(const float4*)&seq[t * 32 + o4 * 4];

    for (int L = 0; L < 2; L++) {
        __syncthreads();
        const float* wqL = wq + L * 1024;
        const float* wkL = wk + L * 1024;
        const float* wvL = wv + L * 1024;
        for (int idx = t; idx < 512; idx += 128) {
            int c = idx >> 4, d = idx & 15;
            Wq2u[c * 16 + d] = pack2(wqL[c * 32 + d], wqL[c * 32 + d + 16]);
            Wk2u[c * 16 + d] = pack2(wkL[c * 32 + d], wkL[c * 32 + d + 16]);
            Wv2u[c * 16 + d] = pack2(wvL[c * 32 + d], wvL[c * 32 + d + 16]);
        }
        __syncthreads();

        u64 qp[16], tv[16];
#pragma unroll
        for (int d = 0; d < 16; d++) qp[d] = 0ULL;
        for (int c = 0; c < 32; c++) {
            u64 hd = pack2(hrow[c], hrow[c]);
#pragma unroll
            for (int j = 0; j < 8; j++) {
                ulonglong2 w = Wq2[c][j];
                qp[2 * j] = fma2(w.x, hd, qp[2 * j]);
                qp[2 * j + 1] = fma2(w.y, hd, qp[2 * j + 1]);
            }
        }
        u64 qsc = pack2(0.25f, 0.25f);
#pragma unroll
        for (int d = 0; d < 16; d++) qp[d] = mul2(qp[d], qsc);

#pragma unroll
        for (int d = 0; d < 16; d++) tv[d] = 0ULL;
        for (int c = 0; c < 32; c++) {
            u64 hd = pack2(hrow[c], hrow[c]);
#pragma unroll
            for (int j = 0; j < 8; j++) {
                ulonglong2 w = Wk2[c][j];
                tv[2 * j] = fma2(w.x, hd, tv[2 * j]);
                tv[2 * j + 1] = fma2(w.y, hd, tv[2 * j + 1]);
            }
        }
#pragma unroll
        for (int j = 0; j < 8; j++)
            Kp[t][j] = make_ulonglong2(tv[2 * j], tv[2 * j + 1]);

#pragma unroll
        for (int d = 0; d < 16; d++) tv[d] = 0ULL;
        for (int c = 0; c < 32; c++) {
            u64 hd = pack2(hrow[c], hrow[c]);
#pragma unroll
            for (int j = 0; j < 8; j++) {
                ulonglong2 w = Wv2[c][j];
                tv[2 * j] = fma2(w.x, hd, tv[2 * j]);
                tv[2 * j + 1] = fma2(w.y, hd, tv[2 * j + 1]);
            }
        }
#pragma unroll
        for (int j = 0; j < 8; j++)
            Vp[t][j] = make_ulonglong2(tv[2 * j], tv[2 * j + 1]);
        __syncthreads();
        const float* woL = wo + L * 1024;
        for (int idx = t; idx < 512; idx += 128) {
            int c = idx >> 4, d = idx & 15;
            Wq2u[c * 16 + d] = pack2(woL[c * 32 + d], woL[c * 32 + d + 16]);
        }

        float m0 = -3e38f, l0 = 0.f, m1 = -3e38f, l1 = 0.f;
        u64 acc[16];
#pragma unroll
        for (int d = 0; d < 16; d++) acc[d] = 0ULL;
        for (int tile = 0; tile < 16; tile++) {
            float sv0[8], sv1[8];
            float ts0 = -3e38f, ts1 = -3e38f;
#pragma unroll
            for (int q = 0; q < 8; q++) {
                int kp = tile * 8 + q;
                u64 s = 0ULL;
#pragma unroll
                for (int j = 0; j < 8; j++) {
                    ulonglong2 k2 = Kp[kp][j];
                    s = fma2(qp[2 * j], k2.x, s);
                    s = fma2(qp[2 * j + 1], k2.y, s);
                }
                unpack2(s, sv0[q], sv1[q]);
                ts0 = fmaxf(ts0, sv0[q]);
                ts1 = fmaxf(ts1, sv1[q]);
            }
            float nm0 = fmaxf(m0, ts0), nm1 = fmaxf(m1, ts1);
            float cf0 = __expf(m0 - nm0), cf1 = __expf(m1 - nm1);
            l0 *= cf0; l1 *= cf1;
            m0 = nm0; m1 = nm1;
            u64 cfp = pack2(cf0, cf1);
#pragma unroll
            for (int d = 0; d < 16; d++) acc[d] = mul2(acc[d], cfp);
#pragma unroll
            for (int q = 0; q < 8; q++) {
                int kp = tile * 8 + q;
                float p0 = __expf(sv0[q] - m0), p1 = __expf(sv1[q] - m1);
                l0 += p0; l1 += p1;
                u64 pp = pack2(p0, p1);
#pragma unroll
                for (int j = 0; j < 8; j++) {
                    ulonglong2 v2 = Vp[kp][j];
                    acc[2 * j] = fma2(pp, v2.x, acc[2 * j]);
                    acc[2 * j + 1] = fma2(pp, v2.y, acc[2 * j + 1]);
                }
            }
        }
        u64 inv = pack2(1.f / l0, 1.f / l1);
        float ov[32];
#pragma unroll
        for (int d = 0; d < 16; d++) {
            u64 a = mul2(acc[d], inv);
            unpack2(a, ov[d], ov[d + 16]);
        }
        __syncthreads();

        u64 rp[16];
#pragma unroll
        for (int d = 0; d < 16; d++)
            rp[d] = pack2(hrow[d], hrow[d + 16]);
        for (int c = 0; c < 32; c++) {
            u64 od = pack2(ov[c], ov[c]);
#pragma unroll
            for (int j = 0; j < 8; j++) {
                ulonglong2 w = Wq2[c][j];
                rp[2 * j] = fma2(w.x, od, rp[2 * j]);
                rp[2 * j + 1] = fma2(w.y, od, rp[2 * j + 1]);
            }
        }
        float r[32];
#pragma unroll
        for (int d = 0; d < 16; d++) unpack2(rp[d], r[d], r[d + 16]);
        float mu = 0.f;
#pragma unroll
        for (int o = 0; o < 32; o++) mu += r[o];
        mu *= (1.f / 32.f);
        float var = 0.f;
#pragma unroll
        for (int o = 0; o < 32; o++) { float d = r[o] - mu; var += d * d; }
        var *= (1.f / 32.f);
        float rs = rsqrtf(var + 1e-5f);
#pragma unroll
        for (int o = 0; o < 32; o++)
            hrow[o] = (r[o] - mu) * rs * gs[L][o] + bs2[L][o];
    }

    int n = blockIdx.x >> 2, b = blockIdx.x & 3;
    float* dst = finalOut + ((b * T_ + t) * N_ + n) * D_;
#pragma unroll
    for (int o4 = 0; o4 < 8; o4++)
        *(float4*)&dst[o4 * 4] =
            make_float4(hrow[o4 * 4], hrow[o4 * 4 + 1],
                        hrow[o4 * 4 + 2], hrow[o4 * 4 + 3]);
}

// ---------------- launcher ---------------------------------------------------
extern "C" void kernel_launch(void* const* d_in, const int* in_sizes, int n_in,
                              void* d_out, int out_size) {
    (void)in_sizes; (void)n_in; (void)out_size;
    const float* x   = (const float*)d_in[0];
    const float* E   = (const float*)d_in[2];
    const float* adj = (const float*)d_in[3];
    const float* gw  = (const float*)d_in[4];
    const float* gb  = (const float*)d_in[5];
    const float* tw1 = (const float*)d_in[6];
    const float* tb1 = (const float*)d_in[7];
    const float* tw2 = (const float*)d_in[8];
    const float* tb2 = (const float*)d_in[9];
    const float* awq = (const float*)d_in[10];
    const float* awk = (const float*)d_in[11];
    const float* awv = (const float*)d_in[12];
    const float* awo = (const float*)d_in[13];
    const float* ag  = (const float*)d_in[14];
    const float* ab  = (const float*)d_in[15];
    float* out = (float*)d_out;

    cudaFuncSetAttribute(k_tcn, cudaFuncAttributeMaxDynamicSharedMemorySize,
                         TCN_SMEM);
    cudaFuncSetAttribute(k_aggM, cudaFuncAttributeMaxDynamicSharedMemorySize,
                         AGG_SMEM);
    cudaFuncSetAttribute(k_combine, cudaFuncAttributeMaxDynamicSharedMemorySize,
                         CMB_SMEM);

    k_transpose<<<dim3(N_, 8), 256>>>(x);
    k_s2<<<dim3(16, 16), 256>>>(adj);
    k_wn<<<dim3(N_, 3), 256>>>(E, gw, gb);
    k_prep<<<512, 256>>>(adj);

    // GCN layer 0: buf0 -> buf1; layer 1: buf1 -> buf0; layer 2: buf0 -> buf1
    k_aggM<<<dim3(128, 8), 256, AGG_SMEM>>>();
    k_combine<<<dim3(N_, 4), 256, CMB_SMEM>>>(0, 0, 1);
    k_aggM<<<dim3(128, 8), 256, AGG_SMEM>>>();
    k_combine<<<dim3(N_, 4), 256, CMB_SMEM>>>(1, 1, 1);
    k_aggM<<<dim3(128, 8), 256, AGG_SMEM>>>();
    k_combine<<<dim3(N_, 4), 256, CMB_SMEM>>>(0, 2, 0);

    // TCN in-place on buf1, 2 sequences per block, o-split across 256 threads
    k_tcn<<<N_ * B_ / 2, 256, TCN_SMEM>>>(tw1, tb1, tw2, tb2, 1);

    // merged 2-layer attention; writes transposed final output
    k_attn2<<<N_ * B_, 128>>>(awq, awk, awv, awo, ag, ab, 1, out);
}

// round 14
// speedup vs baseline: 1.0144x; 1.0144x over previous
#include <cuda_runtime.h>
#include <cuda_bf16.h>

#define B_ 4
#define T_ 128
#define N_ 512
#define D_ 32
#define JN_ 16384       // (B*T)*D
#define EMB_ 10

typedef unsigned long long u64;
typedef unsigned int u32;

// ---------------- f32x2 packed helpers (sm_103a FFMA2) -----------------------
__device__ __forceinline__ u64 pack2(float lo, float hi) {
    u64 r; asm("mov.b64 %0, {%1, %2};" : "=l"(r) : "f"(lo), "f"(hi)); return r;
}
__device__ __forceinline__ void unpack2(u64 v, float& lo, float& hi) {
    asm("mov.b64 {%0, %1}, %2;" : "=f"(lo), "=f"(hi) : "l"(v));
}
__device__ __forceinline__ u64 fma2(u64 a, u64 b, u64 c) {
    u64 d; asm("fma.rn.f32x2 %0, %1, %2, %3;" : "=l"(d) : "l"(a), "l"(b), "l"(c)); return d;
}
__device__ __forceinline__ u64 mul2(u64 a, u64 b) {
    u64 d; asm("mul.rn.f32x2 %0, %1, %2;" : "=l"(d) : "l"(a), "l"(b)); return d;
}
__device__ __forceinline__ u64 add2(u64 a, u64 b) {
    u64 d; asm("add.rn.f32x2 %0, %1, %2;" : "=l"(d) : "l"(a), "l"(b)); return d;
}
__device__ __forceinline__ u64 relu2(u64 v) {
    float a, b; unpack2(v, a, b);
    return pack2(fmaxf(a, 0.f), fmaxf(b, 0.f));
}
__device__ __forceinline__ u32 smem_u32(const void* p) {
    u32 a;
    asm("{ .reg .u64 t; cvta.to.shared.u64 t, %1; cvt.u32.u64 %0, t; }"
        : "=r"(a) : "l"(p));
    return a;
}
// ---------------- mma.sync helpers (sm_80+ path, HMMA on sm_103) ------------
__device__ __forceinline__ void ldmx4(u32& r0, u32& r1, u32& r2, u32& r3, u32 a) {
    asm volatile("ldmatrix.sync.aligned.m8n8.x4.shared.b16 {%0,%1,%2,%3}, [%4];"
                 : "=r"(r0), "=r"(r1), "=r"(r2), "=r"(r3) : "r"(a));
}
__device__ __forceinline__ void ldmx4t(u32& r0, u32& r1, u32& r2, u32& r3, u32 a) {
    asm volatile("ldmatrix.sync.aligned.m8n8.x4.trans.shared.b16 {%0,%1,%2,%3}, [%4];"
                 : "=r"(r0), "=r"(r1), "=r"(r2), "=r"(r3) : "r"(a));
}
__device__ __forceinline__ void mma16816(float* c, const u32* a, const u32* b) {
    asm volatile(
        "mma.sync.aligned.m16n8k16.row.col.f32.bf16.bf16.f32 "
        "{%0,%1,%2,%3}, {%4,%5,%6,%7}, {%8,%9}, {%0,%1,%2,%3};"
        : "+f"(c[0]), "+f"(c[1]), "+f"(c[2]), "+f"(c[3])
        : "r"(a[0]), "r"(a[1]), "r"(a[2]), "r"(a[3]), "r"(b[0]), "r"(b[1]));
}
__device__ __forceinline__ void cpa16(u32 dst, const void* src) {
    asm volatile("cp.async.cg.shared.global [%0], [%1], 16;"
                 :: "r"(dst), "l"(src));
}

// ---------------- scratch (device globals; no allocations allowed) ----------
__device__ float g_buf0[N_ * JN_];       // layout (n, bt, c), bt = b*T+t
__device__ float g_buf1[N_ * JN_];
__device__ float g_xg[2 * N_ * JN_];     // aggregated supports k=1,2
__device__ float g_W[3 * N_ * 3 * D_ * D_];   // per-layer per-node (k,c,o)
__device__ float g_bias[3 * N_ * D_];
// bf16 2-term splits
__device__ __nv_bfloat16 g_A0[1024 * 512], g_A1[1024 * 512];
__device__ __nv_bfloat16 g_B0[N_ * JN_], g_B1[N_ * JN_];

// ---------------- merged setup: transpose | S2 | per-node W | adj split -----
// blockIdx.x ranges: [0,4096) transpose, [4096,4352) S2,
//                    [4352,5888) wn, [5888,6400) adj prep.  256 threads each.
__global__ void __launch_bounds__(256) k_setup(
    const float* __restrict__ x, const float* __restrict__ adj,
    const float* __restrict__ E, const float* __restrict__ gw,
    const float* __restrict__ gb) {
    __shared__ float As[32][33], Bs[32][33];
    int bx = blockIdx.x, tid = threadIdx.x;

    if (bx < 4096) {                       // ---- transpose + bf16 split ----
        int n = bx >> 3, bt0 = (bx & 7) * 64;
#pragma unroll
        for (int j = 0; j < 8; j++) {
            int idx = j * 256 + tid;
            int r = idx >> 5, c = idx & 31;
            float v = x[(bt0 + r) * (N_ * D_) + n * D_ + c];
            int di = n * JN_ + (bt0 + r) * D_ + c;
            g_buf0[di] = v;
            __nv_bfloat16 h = __float2bfloat16_rn(v);
            g_B0[di] = h;
            g_B1[di] = __float2bfloat16_rn(v - __bfloat162float(h));
        }
    } else if (bx < 4352) {                // ---- S2 = 2*adj@adj - I ----
        int q = bx - 4096;
        int by = q >> 4, bxx = q & 15;
        int ty = tid >> 5, tx = tid & 31;
        float acc[4] = {0.f, 0.f, 0.f, 0.f};
        for (int m0 = 0; m0 < N_; m0 += 32) {
#pragma unroll
            for (int i = 0; i < 4; i++) {
                int r = ty + i * 8;
                As[r][tx] = adj[(by * 32 + r) * N_ + m0 + tx];
                Bs[r][tx] = adj[(m0 + r) * N_ + bxx * 32 + tx];
            }
            __syncthreads();
#pragma unroll
            for (int m = 0; m < 32; m++) {
                float b = Bs[m][tx];
#pragma unroll
                for (int i = 0; i < 4; i++) acc[i] += As[ty + i * 8][m] * b;
            }
            __syncthreads();
        }
#pragma unroll
        for (int i = 0; i < 4; i++) {
            int r = by * 32 + ty + i * 8, c = bxx * 32 + tx;
            float v = 2.f * acc[i] - (r == c ? 1.f : 0.f);
            __nv_bfloat16 h = __float2bfloat16_rn(v);
            g_A0[(512 + r) * 512 + c] = h;
            g_A1[(512 + r) * 512 + c] =
                __float2bfloat16_rn(v - __bfloat162float(h));
        }
    } else if (bx < 5888) {                // ---- per-node GCN weights ----
        int q = bx - 4352;
        int n = q & 511, L = q >> 9;
        float Er[EMB_];
#pragma unroll
        for (int e = 0; e < EMB_; e++) Er[e] = E[n * EMB_ + e];
        const float* g0 = gw + L * (EMB_ * 3072);
        float* wout = g_W + (L * N_ + n) * 3072;
        for (int idx = tid; idx < 3072; idx += 256) {
            float a = 0.f;
#pragma unroll
            for (int e = 0; e < EMB_; e++) a += Er[e] * g0[e * 3072 + idx];
            wout[idx] = a;
        }
        if (tid < 32) {
            const float* b0 = gb + L * (EMB_ * 32);
            float a = 0.f;
#pragma unroll
            for (int e = 0; e < EMB_; e++) a += Er[e] * b0[e * 32 + tid];
            g_bias[(L * N_ + n) * 32 + tid] = a;
        }
    } else {                               // ---- adj rows bf16 split ----
        int r = bx - 5888;
        const float* src = &adj[r * 512];
        for (int c = tid; c < 512; c += 256) {
            float v = src[c];
            __nv_bfloat16 h = __float2bfloat16_rn(v);
            g_A0[r * 512 + c] = h;
            g_A1[r * 512 + c] = __float2bfloat16_rn(v - __bfloat162float(h));
        }
    }
}

// ---------------- tensor-core aggregation GEMM via mma.sync -----------------
#define AGG_STAGE 37888
#define AGG_SMEM (2 * AGG_STAGE)    // 75776
__global__ void __launch_bounds__(256) k_aggM() {
    extern __shared__ char smdyn[];
    u32 sbase = smem_u32(smdyn);
    int tid = threadIdx.x, lane = tid & 31, wid = tid >> 5;
    int j0 = blockIdx.x * 128, i0 = blockIdx.y * 128;
    int wm = wid >> 2, wj = wid & 3;
    int lr = lane & 15, lh = lane >> 4;
    float acc[4][4][4];
#pragma unroll
    for (int mt = 0; mt < 4; mt++)
#pragma unroll
        for (int nt = 0; nt < 4; nt++)
#pragma unroll
            for (int q = 0; q < 4; q++) acc[mt][nt][q] = 0.f;

    auto loadStage = [&](int ch, int st) {
        u32 sb = sbase + st * AGG_STAGE;
        int k0 = ch * 32;
#pragma unroll
        for (int it = 0; it < 2; it++) {
            int idx = it * 256 + tid;
            int row = idx >> 2, c16 = idx & 3;
            cpa16(sb + row * 80 + c16 * 16,
                  &g_A0[(i0 + row) * 512 + k0 + c16 * 8]);
            cpa16(sb + 10240 + row * 80 + c16 * 16,
                  &g_A1[(i0 + row) * 512 + k0 + c16 * 8]);
        }
#pragma unroll
        for (int it = 0; it < 2; it++) {
            int idx = it * 256 + tid;
            int k = idx >> 4, c = idx & 15;
            cpa16(sb + 20480 + k * 272 + c * 16,
                  &g_B0[(size_t)(k0 + k) * JN_ + j0 + c * 8]);
            cpa16(sb + 29184 + k * 272 + c * 16,
                  &g_B1[(size_t)(k0 + k) * JN_ + j0 + c * 8]);
        }
        asm volatile("cp.async.commit_group;" ::: "memory");
    };

    loadStage(0, 0);
    for (int ch = 0; ch < 16; ch++) {
        if (ch + 1 < 16) {
            loadStage(ch + 1, (ch + 1) & 1);
            asm volatile("cp.async.wait_group 1;" ::: "memory");
        } else {
            asm volatile("cp.async.wait_group 0;" ::: "memory");
        }
        __syncthreads();
        u32 sb = sbase + (ch & 1) * AGG_STAGE;
        u32 aH = sb, aM = sb + 10240, bH = sb + 20480, bM = sb + 29184;
#pragma unroll
        for (int s2 = 0; s2 < 32; s2 += 16) {
            u32 bh[4][2], bm[4][2];
#pragma unroll
            for (int half = 0; half < 2; half++) {
                u32 boff = (u32)((s2 + lr) * 272 +
                                 (wj * 32 + half * 16 + lh * 8) * 2);
                u32 r0, r1, r2, r3;
                ldmx4t(r0, r1, r2, r3, bH + boff);
                bh[half * 2][0] = r0; bh[half * 2][1] = r1;
                bh[half * 2 + 1][0] = r2; bh[half * 2 + 1][1] = r3;
                ldmx4t(r0, r1, r2, r3, bM + boff);
                bm[half * 2][0] = r0; bm[half * 2][1] = r1;
                bm[half * 2 + 1][0] = r2; bm[half * 2 + 1][1] = r3;
            }
#pragma unroll
            for (int mt = 0; mt < 4; mt++) {
                u32 aoff = (u32)((wm * 64 + mt * 16 + lr) * 80 +
                                 (s2 + lh * 8) * 2);
                u32 ah[4], am[4];
                ldmx4(ah[0], ah[1], ah[2], ah[3], aH + aoff);
                ldmx4(am[0], am[1], am[2], am[3], aM + aoff);
#pragma unroll
                for (int nt = 0; nt < 4; nt++) {
                    mma16816(acc[mt][nt], ah, bh[nt]);
                    mma16816(acc[mt][nt], ah, bm[nt]);
                    mma16816(acc[mt][nt], am, bh[nt]);
                }
            }
        }
        __syncthreads();
    }
    int rbase = i0 + wm * 64 + (lane >> 2);
    int cbase = j0 + wj * 32 + 2 * (lane & 3);
#pragma unroll
    for (int mt = 0; mt < 4; mt++)
#pragma unroll
        for (int nt = 0; nt < 4; nt++) {
            size_t base = (size_t)(rbase + mt * 16) * JN_ + cbase + nt * 8;
            *(float2*)&g_xg[base] = make_float2(acc[mt][nt][0], acc[mt][nt][1]);
            *(float2*)&g_xg[base + 8 * JN_] =
                make_float2(acc[mt][nt][2], acc[mt][nt][3]);
        }
}

// ---------------- combine (R9-proven): out = [H|xg1|xg2] @ W[n] + b[n] ------
__global__ void k_combine(int inSel, int L, int doSplit) {
    __shared__ float Xin[96][68];
    __shared__ float Ws[3072];
    __shared__ float bs[32];
    const float* Hin = inSel ? g_buf1 : g_buf0;
    float* Hout = inSel ? g_buf0 : g_buf1;
    int n = blockIdx.x, bt0 = blockIdx.y * 64, tid = threadIdx.x;
    const float* Wl = g_W + (L * N_ + n) * 3072;
    for (int q = tid; q < 3072; q += 128) Ws[q] = Wl[q];
    if (tid < 32) bs[tid] = g_bias[(L * N_ + n) * 32 + tid];
    const float* s0 = Hin + n * JN_ + bt0 * D_;
    const float* s1 = g_xg + n * JN_ + bt0 * D_;
    const float* s2 = g_xg + (N_ + n) * JN_ + bt0 * D_;
#pragma unroll
    for (int q = tid; q < 2048; q += 128) {
        int r = q >> 5, c = q & 31;
        Xin[c][r] = s0[q];
        Xin[32 + c][r] = s1[q];
        Xin[64 + c][r] = s2[q];
    }
    __syncthreads();
    int to = tid & 7, tb = tid >> 3;
    float acc[4][4];
#pragma unroll
    for (int i = 0; i < 4; i++)
#pragma unroll
        for (int j = 0; j < 4; j++) acc[i][j] = 0.f;
    for (int kc = 0; kc < 96; kc++) {
        float4 xv = *(const float4*)&Xin[kc][tb * 4];
        float4 wv = *(const float4*)&Ws[kc * 32 + to * 4];
        acc[0][0] += xv.x * wv.x; acc[0][1] += xv.x * wv.y;
        acc[0][2] += xv.x * wv.z; acc[0][3] += xv.x * wv.w;
        acc[1][0] += xv.y * wv.x; acc[1][1] += xv.y * wv.y;
        acc[1][2] += xv.y * wv.z; acc[1][3] += xv.y * wv.w;
        acc[2][0] += xv.z * wv.x; acc[2][1] += xv.z * wv.y;
        acc[2][2] += xv.z * wv.z; acc[2][3] += xv.z * wv.w;
        acc[3][0] += xv.w * wv.x; acc[3][1] += xv.w * wv.y;
        acc[3][2] += xv.w * wv.z; acc[3][3] += xv.w * wv.w;
    }
    float4 bv = *(const float4*)&bs[to * 4];
#pragma unroll
    for (int i = 0; i < 4; i++) {
        int bt = bt0 + tb * 4 + i;
        float o0 = acc[i][0] + bv.x, o1 = acc[i][1] + bv.y;
        float o2 = acc[i][2] + bv.z, o3 = acc[i][3] + bv.w;
        int di = n * JN_ + bt * D_ + to * 4;
        *(float4*)&Hout[di] = make_float4(o0, o1, o2, o3);
        if (doSplit) {
            float vv[4] = {o0, o1, o2, o3};
            unsigned short hs[4], ms[4];
#pragma unroll
            for (int q = 0; q < 4; q++) {
                __nv_bfloat16 h = __float2bfloat16_rn(vv[q]);
                hs[q] = __bfloat16_as_ushort(h);
                ms[q] = __bfloat16_as_ushort(
                    __float2bfloat16_rn(vv[q] - __bfloat162float(h)));
            }
            *(uint2*)&g_B0[di] = make_uint2((u32)hs[0] | ((u32)hs[1] << 16),
                                            (u32)hs[2] | ((u32)hs[3] << 16));
            *(uint2*)&g_B1[di] = make_uint2((u32)ms[0] | ((u32)ms[1] << 16),
                                            (u32)ms[2] | ((u32)ms[3] << 16));
        }
    }
}

// ---------------- fused TCN (R9-proven): f32x2, 2 seqs/block, 128 thr -------
#define TCN_SMEM 90880
__global__ void __launch_bounds__(128)
k_tcn(const float* __restrict__ w1, const float* __restrict__ b1,
      const float* __restrict__ w2, const float* __restrict__ b2, int sel) {
    extern __shared__ char dsm[];
    ulonglong2* e01 = (ulonglong2*)dsm;
    u64* wd2 = (u64*)(dsm + 16384);
    u64* bb  = (u64*)(dsm + 16384 + 8192);
    u64 (*y0)[129] = (u64(*)[129])(dsm + 24832);
    u64 (*y1)[129] = (u64(*)[129])(dsm + 24832 + 33024);

    float* base = sel ? g_buf1 : g_buf0;
    float* seqA = base + (2 * blockIdx.x) * 4096;
    float* seqB = seqA + 4096;
    int t = threadIdx.x;

#pragma unroll
    for (int j = 0; j < 32; j++) {
        int idx = j * 128 + t;
        int c = idx & 31, tt = idx >> 5;
        y0[c][tt] = pack2(seqA[idx], seqB[idx]);
    }
    for (int blk = 0; blk < 3; blk++) {
        int dil = 1 << blk;
        __syncthreads();
        const float* ws = w1 + blk * 3072;
        for (int q = t; q < 1024; q += 128) {
            float a = ws[q * 3], b = ws[q * 3 + 1], c = ws[q * 3 + 2];
            e01[q] = make_ulonglong2(pack2(a, a), pack2(b, b));
            wd2[q] = pack2(c, c);
        }
        if (t < 32) { float v = b1[blk * 32 + t]; bb[t] = pack2(v, v); }
        __syncthreads();
        u64 acc[32];
#pragma unroll
        for (int o = 0; o < 32; o++) acc[o] = bb[o];
        for (int c = 0; c < 32; c++) {
            u64 i0 = (t >= 2 * dil) ? y0[c][t - 2 * dil] : 0ULL;
            u64 i1 = (t >= dil) ? y0[c][t - dil] : 0ULL;
            u64 i2 = y0[c][t];
#pragma unroll
            for (int o = 0; o < 32; o++) {
                ulonglong2 w01 = e01[o * 32 + c];
                acc[o] = fma2(w01.x, i0, acc[o]);
                acc[o] = fma2(w01.y, i1, acc[o]);
                acc[o] = fma2(wd2[o * 32 + c], i2, acc[o]);
            }
        }
#pragma unroll
        for (int o = 0; o < 32; o++) y1[o][t] = relu2(acc[o]);
        __syncthreads();
        const float* ws2 = w2 + blk * 3072;
        for (int q = t; q < 1024; q += 128) {
            float a = ws2[q * 3], b = ws2[q * 3 + 1], c = ws2[q * 3 + 2];
            e01[q] = make_ulonglong2(pack2(a, a), pack2(b, b));
            wd2[q] = pack2(c, c);
        }
        if (t < 32) { float v = b2[blk * 32 + t]; bb[t] = pack2(v, v); }
        __syncthreads();
#pragma unroll
        for (int o = 0; o < 32; o++) acc[o] = bb[o];
        for (int c = 0; c < 32; c++) {
            u64 i0 = (t >= 2 * dil) ? y1[c][t - 2 * dil] : 0ULL;
            u64 i1 = (t >= dil) ? y1[c][t - dil] : 0ULL;
            u64 i2 = y1[c][t];
#pragma unroll
            for (int o = 0; o < 32; o++) {
                ulonglong2 w01 = e01[o * 32 + c];
                acc[o] = fma2(w01.x, i0, acc[o]);
                acc[o] = fma2(w01.y, i1, acc[o]);
                acc[o] = fma2(wd2[o * 32 + c], i2, acc[o]);
            }
        }
#pragma unroll
        for (int o = 0; o < 32; o++)
            y0[o][t] = relu2(add2(relu2(acc[o]), y0[o][t]));
    }
    __syncthreads();
#pragma unroll
    for (int j = 0; j < 32; j++) {
        int idx = j * 128 + t;
        int c = idx & 31, tt = idx >> 5;
        float lo, hi; unpack2(y0[c][tt], lo, hi);
        seqA[idx] = lo; seqB[idx] = hi;
    }
}

// ---------------- merged 2-layer temporal attention + layernorm -------------
__global__ void __launch_bounds__(128)
k_attn2(const float* __restrict__ wq, const float* __restrict__ wk,
        const float* __restrict__ wv, const float* __restrict__ wo,
        const float* __restrict__ gga, const float* __restrict__ bba,
        int sel, float* __restrict__ finalOut) {
    __shared__ ulonglong2 Kp[128][8];
    __shared__ ulonglong2 Vp[128][8];
    __shared__ ulonglong2 Wq2[32][8];   // reused for Wo
    __shared__ ulonglong2 Wk2[32][8];
    __shared__ ulonglong2 Wv2[32][8];
    __shared__ float gs[2][32], bs2[2][32];
    const float* seq = (sel ? g_buf1 : g_buf0) + blockIdx.x * 4096;
    int t = threadIdx.x;
    u64* Wq2u = (u64*)Wq2; u64* Wk2u = (u64*)Wk2; u64* Wv2u = (u64*)Wv2;

    if (t < 64) {
        int L = t >> 5, o = t & 31;
        gs[L][o] = gga[L * 32 + o];
        bs2[L][o] = bba[L * 32 + o];
    }
    float hrow[32];
#pragma unroll
    for (int o4 = 0; o4 < 8; o4++)
        *(float4*)&hrow[o4 * 4] = *(const float4*)&seq[t * 32 + o4 * 4];

    for (int L = 0; L < 2; L++) {
        __syncthreads();
        const float* wqL = wq + L * 1024;
        const float* wkL = wk + L * 1024;
        const float* wvL = wv + L * 1024;
        for (int idx = t; idx < 512; idx += 128) {
            int c = idx >> 4, d = idx & 15;
            Wq2u[c * 16 + d] = pack2(wqL[c * 32 + d], wqL[c * 32 + d + 16]);
            Wk2u[c * 16 + d] = pack2(wkL[c * 32 + d], wkL[c * 32 + d + 16]);
            Wv2u[c * 16 + d] = pack2(wvL[c * 32 + d], wvL[c * 32 + d + 16]);
        }
        __syncthreads();

        u64 qp[16], tv[16];
#pragma unroll
        for (int d = 0; d < 16; d++) qp[d] = 0ULL;
        for (int c = 0; c < 32; c++) {
            u64 hd = pack2(hrow[c], hrow[c]);
#pragma unroll
            for (int j = 0; j < 8; j++) {
                ulonglong2 w = Wq2[c][j];
                qp[2 * j] = fma2(w.x, hd, qp[2 * j]);
                qp[2 * j + 1] = fma2(w.y, hd, qp[2 * j + 1]);
            }
        }
        u64 qsc = pack2(0.25f, 0.25f);
#pragma unroll
        for (int d = 0; d < 16; d++) qp[d] = mul2(qp[d], qsc);

#pragma unroll
        for (int d = 0; d < 16; d++) tv[d] = 0ULL;
        for (int c = 0; c < 32; c++) {
            u64 hd = pack2(hrow[c], hrow[c]);
#pragma unroll
            for (int j = 0; j < 8; j++) {
                ulonglong2 w = Wk2[c][j];
                tv[2 * j] = fma2(w.x, hd, tv[2 * j]);
                tv[2 * j + 1] = fma2(w.y, hd, tv[2 * j + 1]);
            }
        }
#pragma unroll
        for (int j = 0; j < 8; j++)
            Kp[t][j] = make_ulonglong2(tv[2 * j], tv[2 * j + 1]);

#pragma unroll
        for (int d = 0; d < 16; d++) tv[d] = 0ULL;
        for (int c = 0; c < 32; c++) {
            u64 hd = pack2(hrow[c], hrow[c]);
#pragma unroll
            for (int j = 0; j < 8; j++) {
                ulonglong2 w = Wv2[c][j];
                tv[2 * j] = fma2(w.x, hd, tv[2 * j]);
                tv[2 * j + 1] = fma2(w.y, hd, tv[2 * j + 1]);
            }
        }
#pragma unroll
        for (int j = 0; j < 8; j++)
            Vp[t][j] = make_ulonglong2(tv[2 * j], tv[2 * j + 1]);
        __syncthreads();
        const float* woL = wo + L * 1024;
        for (int idx = t; idx < 512; idx += 128) {
            int c = idx >> 4, d = idx & 15;
            Wq2u[c * 16 + d] = pack2(woL[c * 32 + d], woL[c * 32 + d + 16]);
        }

        float m0 = -3e38f, l0 = 0.f, m1 = -3e38f, l1 = 0.f;
        u64 acc[16];
#pragma unroll
        for (int d = 0; d < 16; d++) acc[d] = 0ULL;
        for (int tile = 0; tile < 16; tile++) {
            float sv0[8], sv1[8];
            float ts0 = -3e38f, ts1 = -3e38f;
#pragma unroll
            for (int q = 0; q < 8; q++) {
                int kp = tile * 8 + q;
                u64 s = 0ULL;
#pragma unroll
                for (int j = 0; j < 8; j++) {
                    ulonglong2 k2 = Kp[kp][j];
                    s = fma2(qp[2 * j], k2.x, s);
                    s = fma2(qp[2 * j + 1], k2.y, s);
                }
                unpack2(s, sv0[q], sv1[q]);
                ts0 = fmaxf(ts0, sv0[q]);
                ts1 = fmaxf(ts1, sv1[q]);
            }
            float nm0 = fmaxf(m0, ts0), nm1 = fmaxf(m1, ts1);
            float cf0 = __expf(m0 - nm0), cf1 = __expf(m1 - nm1);
            l0 *= cf0; l1 *= cf1;
            m0 = nm0; m1 = nm1;
            u64 cfp = pack2(cf0, cf1);
#pragma unroll
            for (int d = 0; d < 16; d++) acc[d] = mul2(acc[d], cfp);
#pragma unroll
            for (int q = 0; q < 8; q++) {
                int kp = tile * 8 + q;
                float p0 = __expf(sv0[q] - m0), p1 = __expf(sv1[q] - m1);
                l0 += p0; l1 += p1;
                u64 pp = pack2(p0, p1);
#pragma unroll
                for (int j = 0; j < 8; j++) {
                    ulonglong2 v2 = Vp[kp][j];
                    acc[2 * j] = fma2(pp, v2.x, acc[2 * j]);
                    acc[2 * j + 1] = fma2(pp, v2.y, acc[2 * j + 1]);
                }
            }
        }
        u64 inv = pack2(1.f / l0, 1.f / l1);
        float ov[32];
#pragma unroll
        for (int d = 0; d < 16; d++) {
            u64 a = mul2(acc[d], inv);
            unpack2(a, ov[d], ov[d + 16]);
        }
        __syncthreads();

        u64 rp[16];
#pragma unroll
        for (int d = 0; d < 16; d++)
            rp[d] = pack2(hrow[d], hrow[d + 16]);
        for (int c = 0; c < 32; c++) {
            u64 od = pack2(ov[c], ov[c]);
#pragma unroll
            for (int j = 0; j < 8; j++) {
                ulonglong2 w = Wq2[c][j];
                rp[2 * j] = fma2(w.x, od, rp[2 * j]);
                rp[2 * j + 1] = fma2(w.y, od, rp[2 * j + 1]);
            }
        }
        float r[32];
#pragma unroll
        for (int d = 0; d < 16; d++) unpack2(rp[d], r[d], r[d + 16]);
        float mu = 0.f;
#pragma unroll
        for (int o = 0; o < 32; o++) mu += r[o];
        mu *= (1.f / 32.f);
        float var = 0.f;
#pragma unroll
        for (int o = 0; o < 32; o++) { float d = r[o] - mu; var += d * d; }
        var *= (1.f / 32.f);
        float rs = rsqrtf(var + 1e-5f);
#pragma unroll
        for (int o = 0; o < 32; o++)
            hrow[o] = (r[o] - mu) * rs * gs[L][o] + bs2[L][o];
    }

    int n = blockIdx.x >> 2, b = blockIdx.x & 3;
    float* dst = finalOut + ((b * T_ + t) * N_ + n) * D_;
#pragma unroll
    for (int o4 = 0; o4 < 8; o4++)
        *(float4*)&dst[o4 * 4] =
            make_float4(hrow[o4 * 4], hrow[o4 * 4 + 1],
                        hrow[o4 * 4 + 2], hrow[o4 * 4 + 3]);
}

// ---------------- launcher ---------------------------------------------------
extern "C" void kernel_launch(void* const* d_in, const int* in_sizes, int n_in,
                              void* d_out, int out_size) {
    (void)in_sizes; (void)n_in; (void)out_size;
    const float* x   = (const float*)d_in[0];
    const float* E   = (const float*)d_in[2];
    const float* adj = (const float*)d_in[3];
    const float* gw  = (const float*)d_in[4];
    const float* gb  = (const float*)d_in[5];
    const float* tw1 = (const float*)d_in[6];
    const float* tb1 = (const float*)d_in[7];
    const float* tw2 = (const float*)d_in[8];
    const float* tb2 = (const float*)d_in[9];
    const float* awq = (const float*)d_in[10];
    const float* awk = (const float*)d_in[11];
    const float* awv = (const float*)d_in[12];
    const float* awo = (const float*)d_in[13];
    const float* ag  = (const float*)d_in[14];
    const float* ab  = (const float*)d_in[15];
    float* out = (float*)d_out;

    cudaFuncSetAttribute(k_tcn, cudaFuncAttributeMaxDynamicSharedMemorySize,
                         TCN_SMEM);
    cudaFuncSetAttribute(k_aggM, cudaFuncAttributeMaxDynamicSharedMemorySize,
                         AGG_SMEM);

    // merged setup: transpose | S2 | wn | adj split in one launch
    k_setup<<<6400, 256>>>(x, adj, E, gw, gb);

    // GCN layer 0: buf0 -> buf1; layer 1: buf1 -> buf0; layer 2: buf0 -> buf1
    k_aggM<<<dim3(128, 8), 256, AGG_SMEM>>>();
    k_combine<<<dim3(N_, 8), 128>>>(0, 0, 1);
    k_aggM<<<dim3(128, 8), 256, AGG_SMEM>>>();
    k_combine<<<dim3(N_, 8), 128>>>(1, 1, 1);
    k_aggM<<<dim3(128, 8), 256, AGG_SMEM>>>();
    k_combine<<<dim3(N_, 8), 128>>>(0, 2, 0);

    // TCN in-place on buf1, 2 sequences per block
    k_tcn<<<N_ * B_ / 2, 128, TCN_SMEM>>>(tw1, tb1, tw2, tb2, 1);

    // merged 2-layer attention; writes transposed final output
    k_attn2<<<N_ * B_, 128>>>(awq, awk, awv, awo, ag, ab, 1, out);
}

// round 15
// speedup vs baseline: 1.0150x; 1.0005x over previous
#include <cuda_runtime.h>
#include <cuda_bf16.h>

#define B_ 4
#define T_ 128
#define N_ 512
#define D_ 32
#define JN_ 16384       // (B*T)*D
#define EMB_ 10

typedef unsigned long long u64;
typedef unsigned int u32;

// ---------------- f32x2 packed helpers (sm_103a FFMA2) -----------------------
__device__ __forceinline__ u64 pack2(float lo, float hi) {
    u64 r; asm("mov.b64 %0, {%1, %2};" : "=l"(r) : "f"(lo), "f"(hi)); return r;
}
__device__ __forceinline__ void unpack2(u64 v, float& lo, float& hi) {
    asm("mov.b64 {%0, %1}, %2;" : "=f"(lo), "=f"(hi) : "l"(v));
}
__device__ __forceinline__ u64 fma2(u64 a, u64 b, u64 c) {
    u64 d; asm("fma.rn.f32x2 %0, %1, %2, %3;" : "=l"(d) : "l"(a), "l"(b), "l"(c)); return d;
}
__device__ __forceinline__ u64 mul2(u64 a, u64 b) {
    u64 d; asm("mul.rn.f32x2 %0, %1, %2;" : "=l"(d) : "l"(a), "l"(b)); return d;
}
__device__ __forceinline__ u64 add2(u64 a, u64 b) {
    u64 d; asm("add.rn.f32x2 %0, %1, %2;" : "=l"(d) : "l"(a), "l"(b)); return d;
}
__device__ __forceinline__ u64 relu2(u64 v) {
    float a, b; unpack2(v, a, b);
    return pack2(fmaxf(a, 0.f), fmaxf(b, 0.f));
}
__device__ __forceinline__ u32 smem_u32(const void* p) {
    u32 a;
    asm("{ .reg .u64 t; cvta.to.shared.u64 t, %1; cvt.u32.u64 %0, t; }"
        : "=r"(a) : "l"(p));
    return a;
}
// ---------------- mma.sync helpers (sm_80+ path, HMMA on sm_103) ------------
__device__ __forceinline__ void ldmx4(u32& r0, u32& r1, u32& r2, u32& r3, u32 a) {
    asm volatile("ldmatrix.sync.aligned.m8n8.x4.shared.b16 {%0,%1,%2,%3}, [%4];"
                 : "=r"(r0), "=r"(r1), "=r"(r2), "=r"(r3) : "r"(a));
}
__device__ __forceinline__ void ldmx4t(u32& r0, u32& r1, u32& r2, u32& r3, u32 a) {
    asm volatile("ldmatrix.sync.aligned.m8n8.x4.trans.shared.b16 {%0,%1,%2,%3}, [%4];"
                 : "=r"(r0), "=r"(r1), "=r"(r2), "=r"(r3) : "r"(a));
}
__device__ __forceinline__ void mma16816(float* c, const u32* a, const u32* b) {
    asm volatile(
        "mma.sync.aligned.m16n8k16.row.col.f32.bf16.bf16.f32 "
        "{%0,%1,%2,%3}, {%4,%5,%6,%7}, {%8,%9}, {%0,%1,%2,%3};"
        : "+f"(c[0]), "+f"(c[1]), "+f"(c[2]), "+f"(c[3])
        : "r"(a[0]), "r"(a[1]), "r"(a[2]), "r"(a[3]), "r"(b[0]), "r"(b[1]));
}
__device__ __forceinline__ void cpa16(u32 dst, const void* src) {
    asm volatile("cp.async.cg.shared.global [%0], [%1], 16;"
                 :: "r"(dst), "l"(src));
}

// ---------------- scratch (device globals; no allocations allowed) ----------
__device__ float g_buf0[N_ * JN_];       // layout (n, bt, c), bt = b*T+t
__device__ float g_buf1[N_ * JN_];
__device__ float g_xg[2 * N_ * JN_];     // aggregated supports k=1,2
__device__ float g_W[3 * N_ * 3 * D_ * D_];   // per-layer per-node (k,c,o)
__device__ float g_bias[3 * N_ * D_];
// bf16 2-term splits
__device__ __nv_bfloat16 g_A0[1024 * 512], g_A1[1024 * 512];
__device__ __nv_bfloat16 g_B0[N_ * JN_], g_B1[N_ * JN_];

// ---------------- merged setup: transpose | S2 | per-node W | adj split -----
__global__ void __launch_bounds__(256) k_setup(
    const float* __restrict__ x, const float* __restrict__ adj,
    const float* __restrict__ E, const float* __restrict__ gw,
    const float* __restrict__ gb) {
    __shared__ float As[32][33], Bs[32][33];
    int bx = blockIdx.x, tid = threadIdx.x;

    if (bx < 4096) {                       // ---- transpose + bf16 split ----
        int n = bx >> 3, bt0 = (bx & 7) * 64;
#pragma unroll
        for (int j = 0; j < 8; j++) {
            int idx = j * 256 + tid;
            int r = idx >> 5, c = idx & 31;
            float v = x[(bt0 + r) * (N_ * D_) + n * D_ + c];
            int di = n * JN_ + (bt0 + r) * D_ + c;
            g_buf0[di] = v;
            __nv_bfloat16 h = __float2bfloat16_rn(v);
            g_B0[di] = h;
            g_B1[di] = __float2bfloat16_rn(v - __bfloat162float(h));
        }
    } else if (bx < 4352) {                // ---- S2 = 2*adj@adj - I ----
        int q = bx - 4096;
        int by = q >> 4, bxx = q & 15;
        int ty = tid >> 5, tx = tid & 31;
        float acc[4] = {0.f, 0.f, 0.f, 0.f};
        for (int m0 = 0; m0 < N_; m0 += 32) {
#pragma unroll
            for (int i = 0; i < 4; i++) {
                int r = ty + i * 8;
                As[r][tx] = adj[(by * 32 + r) * N_ + m0 + tx];
                Bs[r][tx] = adj[(m0 + r) * N_ + bxx * 32 + tx];
            }
            __syncthreads();
#pragma unroll
            for (int m = 0; m < 32; m++) {
                float b = Bs[m][tx];
#pragma unroll
                for (int i = 0; i < 4; i++) acc[i] += As[ty + i * 8][m] * b;
            }
            __syncthreads();
        }
#pragma unroll
        for (int i = 0; i < 4; i++) {
            int r = by * 32 + ty + i * 8, c = bxx * 32 + tx;
            float v = 2.f * acc[i] - (r == c ? 1.f : 0.f);
            __nv_bfloat16 h = __float2bfloat16_rn(v);
            g_A0[(512 + r) * 512 + c] = h;
            g_A1[(512 + r) * 512 + c] =
                __float2bfloat16_rn(v - __bfloat162float(h));
        }
    } else if (bx < 5888) {                // ---- per-node GCN weights ----
        int q = bx - 4352;
        int n = q & 511, L = q >> 9;
        float Er[EMB_];
#pragma unroll
        for (int e = 0; e < EMB_; e++) Er[e] = E[n * EMB_ + e];
        const float* g0 = gw + L * (EMB_ * 3072);
        float* wout = g_W + (L * N_ + n) * 3072;
        for (int idx = tid; idx < 3072; idx += 256) {
            float a = 0.f;
#pragma unroll
            for (int e = 0; e < EMB_; e++) a += Er[e] * g0[e * 3072 + idx];
            wout[idx] = a;
        }
        if (tid < 32) {
            const float* b0 = gb + L * (EMB_ * 32);
            float a = 0.f;
#pragma unroll
            for (int e = 0; e < EMB_; e++) a += Er[e] * b0[e * 32 + tid];
            g_bias[(L * N_ + n) * 32 + tid] = a;
        }
    } else {                               // ---- adj rows bf16 split ----
        int r = bx - 5888;
        const float* src = &adj[r * 512];
        for (int c = tid; c < 512; c += 256) {
            float v = src[c];
            __nv_bfloat16 h = __float2bfloat16_rn(v);
            g_A0[r * 512 + c] = h;
            g_A1[r * 512 + c] = __float2bfloat16_rn(v - __bfloat162float(h));
        }
    }
}

// ---------------- tensor-core aggregation GEMM via mma.sync -----------------
#define AGG_STAGE 37888
#define AGG_SMEM (2 * AGG_STAGE)    // 75776
__global__ void __launch_bounds__(256) k_aggM() {
    extern __shared__ char smdyn[];
    u32 sbase = smem_u32(smdyn);
    int tid = threadIdx.x, lane = tid & 31, wid = tid >> 5;
    int j0 = blockIdx.x * 128, i0 = blockIdx.y * 128;
    int wm = wid >> 2, wj = wid & 3;
    int lr = lane & 15, lh = lane >> 4;
    float acc[4][4][4];
#pragma unroll
    for (int mt = 0; mt < 4; mt++)
#pragma unroll
        for (int nt = 0; nt < 4; nt++)
#pragma unroll
            for (int q = 0; q < 4; q++) acc[mt][nt][q] = 0.f;

    auto loadStage = [&](int ch, int st) {
        u32 sb = sbase + st * AGG_STAGE;
        int k0 = ch * 32;
#pragma unroll
        for (int it = 0; it < 2; it++) {
            int idx = it * 256 + tid;
            int row = idx >> 2, c16 = idx & 3;
            cpa16(sb + row * 80 + c16 * 16,
                  &g_A0[(i0 + row) * 512 + k0 + c16 * 8]);
            cpa16(sb + 10240 + row * 80 + c16 * 16,
                  &g_A1[(i0 + row) * 512 + k0 + c16 * 8]);
        }
#pragma unroll
        for (int it = 0; it < 2; it++) {
            int idx = it * 256 + tid;
            int k = idx >> 4, c = idx & 15;
            cpa16(sb + 20480 + k * 272 + c * 16,
                  &g_B0[(size_t)(k0 + k) * JN_ + j0 + c * 8]);
            cpa16(sb + 29184 + k * 272 + c * 16,
                  &g_B1[(size_t)(k0 + k) * JN_ + j0 + c * 8]);
        }
        asm volatile("cp.async.commit_group;" ::: "memory");
    };

    loadStage(0, 0);
    for (int ch = 0; ch < 16; ch++) {
        if (ch + 1 < 16) {
            loadStage(ch + 1, (ch + 1) & 1);
            asm volatile("cp.async.wait_group 1;" ::: "memory");
        } else {
            asm volatile("cp.async.wait_group 0;" ::: "memory");
        }
        __syncthreads();
        u32 sb = sbase + (ch & 1) * AGG_STAGE;
        u32 aH = sb, aM = sb + 10240, bH = sb + 20480, bM = sb + 29184;
#pragma unroll
        for (int s2 = 0; s2 < 32; s2 += 16) {
            u32 bh[4][2], bm[4][2];
#pragma unroll
            for (int half = 0; half < 2; half++) {
                u32 boff = (u32)((s2 + lr) * 272 +
                                 (wj * 32 + half * 16 + lh * 8) * 2);
                u32 r0, r1, r2, r3;
                ldmx4t(r0, r1, r2, r3, bH + boff);
                bh[half * 2][0] = r0; bh[half * 2][1] = r1;
                bh[half * 2 + 1][0] = r2; bh[half * 2 + 1][1] = r3;
                ldmx4t(r0, r1, r2, r3, bM + boff);
                bm[half * 2][0] = r0; bm[half * 2][1] = r1;
                bm[half * 2 + 1][0] = r2; bm[half * 2 + 1][1] = r3;
            }
#pragma unroll
            for (int mt = 0; mt < 4; mt++) {
                u32 aoff = (u32)((wm * 64 + mt * 16 + lr) * 80 +
                                 (s2 + lh * 8) * 2);
                u32 ah[4], am[4];
                ldmx4(ah[0], ah[1], ah[2], ah[3], aH + aoff);
                ldmx4(am[0], am[1], am[2], am[3], aM + aoff);
#pragma unroll
                for (int nt = 0; nt < 4; nt++) {
                    mma16816(acc[mt][nt], ah, bh[nt]);
                    mma16816(acc[mt][nt], ah, bm[nt]);
                    mma16816(acc[mt][nt], am, bh[nt]);
                }
            }
        }
        __syncthreads();
    }
    int rbase = i0 + wm * 64 + (lane >> 2);
    int cbase = j0 + wj * 32 + 2 * (lane & 3);
#pragma unroll
    for (int mt = 0; mt < 4; mt++)
#pragma unroll
        for (int nt = 0; nt < 4; nt++) {
            size_t base = (size_t)(rbase + mt * 16) * JN_ + cbase + nt * 8;
            *(float2*)&g_xg[base] = make_float2(acc[mt][nt][0], acc[mt][nt][1]);
            *(float2*)&g_xg[base + 8 * JN_] =
                make_float2(acc[mt][nt][2], acc[mt][nt][3]);
        }
}

// ---------------- combine (R9-proven): out = [H|xg1|xg2] @ W[n] + b[n] ------
__global__ void k_combine(int inSel, int L, int doSplit) {
    __shared__ float Xin[96][68];
    __shared__ float Ws[3072];
    __shared__ float bs[32];
    const float* Hin = inSel ? g_buf1 : g_buf0;
    float* Hout = inSel ? g_buf0 : g_buf1;
    int n = blockIdx.x, bt0 = blockIdx.y * 64, tid = threadIdx.x;
    const float* Wl = g_W + (L * N_ + n) * 3072;
    for (int q = tid; q < 3072; q += 128) Ws[q] = Wl[q];
    if (tid < 32) bs[tid] = g_bias[(L * N_ + n) * 32 + tid];
    const float* s0 = Hin + n * JN_ + bt0 * D_;
    const float* s1 = g_xg + n * JN_ + bt0 * D_;
    const float* s2 = g_xg + (N_ + n) * JN_ + bt0 * D_;
#pragma unroll
    for (int q = tid; q < 2048; q += 128) {
        int r = q >> 5, c = q & 31;
        Xin[c][r] = s0[q];
        Xin[32 + c][r] = s1[q];
        Xin[64 + c][r] = s2[q];
    }
    __syncthreads();
    int to = tid & 7, tb = tid >> 3;
    float acc[4][4];
#pragma unroll
    for (int i = 0; i < 4; i++)
#pragma unroll
        for (int j = 0; j < 4; j++) acc[i][j] = 0.f;
    for (int kc = 0; kc < 96; kc++) {
        float4 xv = *(const float4*)&Xin[kc][tb * 4];
        float4 wv = *(const float4*)&Ws[kc * 32 + to * 4];
        acc[0][0] += xv.x * wv.x; acc[0][1] += xv.x * wv.y;
        acc[0][2] += xv.x * wv.z; acc[0][3] += xv.x * wv.w;
        acc[1][0] += xv.y * wv.x; acc[1][1] += xv.y * wv.y;
        acc[1][2] += xv.y * wv.z; acc[1][3] += xv.y * wv.w;
        acc[2][0] += xv.z * wv.x; acc[2][1] += xv.z * wv.y;
        acc[2][2] += xv.z * wv.z; acc[2][3] += xv.z * wv.w;
        acc[3][0] += xv.w * wv.x; acc[3][1] += xv.w * wv.y;
        acc[3][2] += xv.w * wv.z; acc[3][3] += xv.w * wv.w;
    }
    float4 bv = *(const float4*)&bs[to * 4];
#pragma unroll
    for (int i = 0; i < 4; i++) {
        int bt = bt0 + tb * 4 + i;
        float o0 = acc[i][0] + bv.x, o1 = acc[i][1] + bv.y;
        float o2 = acc[i][2] + bv.z, o3 = acc[i][3] + bv.w;
        int di = n * JN_ + bt * D_ + to * 4;
        *(float4*)&Hout[di] = make_float4(o0, o1, o2, o3);
        if (doSplit) {
            float vv[4] = {o0, o1, o2, o3};
            unsigned short hs[4], ms[4];
#pragma unroll
            for (int q = 0; q < 4; q++) {
                __nv_bfloat16 h = __float2bfloat16_rn(vv[q]);
                hs[q] = __bfloat16_as_ushort(h);
                ms[q] = __bfloat16_as_ushort(
                    __float2bfloat16_rn(vv[q] - __bfloat162float(h)));
            }
            *(uint2*)&g_B0[di] = make_uint2((u32)hs[0] | ((u32)hs[1] << 16),
                                            (u32)hs[2] | ((u32)hs[3] << 16));
            *(uint2*)&g_B1[di] = make_uint2((u32)ms[0] | ((u32)ms[1] << 16),
                                            (u32)ms[2] | ((u32)ms[3] << 16));
        }
    }
}

// ---------------- fused TCN (R9-proven): f32x2, 2 seqs/block, 128 thr -------
#define TCN_SMEM 90880
__global__ void __launch_bounds__(128)
k_tcn(const float* __restrict__ w1, const float* __restrict__ b1,
      const float* __restrict__ w2, const float* __restrict__ b2, int sel) {
    extern __shared__ char dsm[];
    ulonglong2* e01 = (ulonglong2*)dsm;
    u64* wd2 = (u64*)(dsm + 16384);
    u64* bb  = (u64*)(dsm + 16384 + 8192);
    u64 (*y0)[129] = (u64(*)[129])(dsm + 24832);
    u64 (*y1)[129] = (u64(*)[129])(dsm + 24832 + 33024);

    float* base = sel ? g_buf1 : g_buf0;
    float* seqA = base + (2 * blockIdx.x) * 4096;
    float* seqB = seqA + 4096;
    int t = threadIdx.x;

#pragma unroll
    for (int j = 0; j < 32; j++) {
        int idx = j * 128 + t;
        int c = idx & 31, tt = idx >> 5;
        y0[c][tt] = pack2(seqA[idx], seqB[idx]);
    }
    for (int blk = 0; blk < 3; blk++) {
        int dil = 1 << blk;
        __syncthreads();
        const float* ws = w1 + blk * 3072;
        for (int q = t; q < 1024; q += 128) {
            float a = ws[q * 3], b = ws[q * 3 + 1], c = ws[q * 3 + 2];
            e01[q] = make_ulonglong2(pack2(a, a), pack2(b, b));
            wd2[q] = pack2(c, c);
        }
        if (t < 32) { float v = b1[blk * 32 + t]; bb[t] = pack2(v, v); }
        __syncthreads();
        u64 acc[32];
#pragma unroll
        for (int o = 0; o < 32; o++) acc[o] = bb[o];
        for (int c = 0; c < 32; c++) {
            u64 i0 = (t >= 2 * dil) ? y0[c][t - 2 * dil] : 0ULL;
            u64 i1 = (t >= dil) ? y0[c][t - dil] : 0ULL;
            u64 i2 = y0[c][t];
#pragma unroll
            for (int o = 0; o < 32; o++) {
                ulonglong2 w01 = e01[o * 32 + c];
                acc[o] = fma2(w01.x, i0, acc[o]);
                acc[o] = fma2(w01.y, i1, acc[o]);
                acc[o] = fma2(wd2[o * 32 + c], i2, acc[o]);
            }
        }
#pragma unroll
        for (int o = 0; o < 32; o++) y1[o][t] = relu2(acc[o]);
        __syncthreads();
        const float* ws2 = w2 + blk * 3072;
        for (int q = t; q < 1024; q += 128) {
            float a = ws2[q * 3], b = ws2[q * 3 + 1], c = ws2[q * 3 + 2];
            e01[q] = make_ulonglong2(pack2(a, a), pack2(b, b));
            wd2[q] = pack2(c, c);
        }
        if (t < 32) { float v = b2[blk * 32 + t]; bb[t] = pack2(v, v); }
        __syncthreads();
#pragma unroll
        for (int o = 0; o < 32; o++) acc[o] = bb[o];
        for (int c = 0; c < 32; c++) {
            u64 i0 = (t >= 2 * dil) ? y1[c][t - 2 * dil] : 0ULL;
            u64 i1 = (t >= dil) ? y1[c][t - dil] : 0ULL;
            u64 i2 = y1[c][t];
#pragma unroll
            for (int o = 0; o < 32; o++) {
                ulonglong2 w01 = e01[o * 32 + c];
                acc[o] = fma2(w01.x, i0, acc[o]);
                acc[o] = fma2(w01.y, i1, acc[o]);
                acc[o] = fma2(wd2[o * 32 + c], i2, acc[o]);
            }
        }
#pragma unroll
        for (int o = 0; o < 32; o++)
            y0[o][t] = relu2(add2(relu2(acc[o]), y0[o][t]));
    }
    __syncthreads();
#pragma unroll
    for (int j = 0; j < 32; j++) {
        int idx = j * 128 + t;
        int c = idx & 31, tt = idx >> 5;
        float lo, hi; unpack2(y0[c][tt], lo, hi);
        seqA[idx] = lo; seqB[idx] = hi;
    }
}

// ---------------- merged 2-layer attention, 2 sequences per block -----------
// dynamic smem: Kp[2](32KB) Vp[2](32KB) W tiles(12KB) = 77824 B
#define ATT_SMEM (2 * 16384 + 2 * 16384 + 3 * 4096)
__global__ void __launch_bounds__(256)
k_attn2(const float* __restrict__ wq, const float* __restrict__ wk,
        const float* __restrict__ wv, const float* __restrict__ wo,
        const float* __restrict__ gga, const float* __restrict__ bba,
        int sel, float* __restrict__ finalOut) {
    extern __shared__ char asm_[];
    ulonglong2 (*KpA)[8] = (ulonglong2(*)[8])asm_;                 // [2][128][8]
    ulonglong2 (*VpA)[8] = (ulonglong2(*)[8])(asm_ + 32768);       // [2][128][8]
    ulonglong2 (*Wq2)[8] = (ulonglong2(*)[8])(asm_ + 65536);       // [32][8] (Wo reuse)
    ulonglong2 (*Wk2)[8] = (ulonglong2(*)[8])(asm_ + 65536 + 4096);
    ulonglong2 (*Wv2)[8] = (ulonglong2(*)[8])(asm_ + 65536 + 8192);
    __shared__ float gs[2][32], bs2[2][32];
    int tid = threadIdx.x;
    int sHalf = tid >> 7, t = tid & 127;
    int sIdx = 2 * blockIdx.x + sHalf;
    const float* seq = (sel ? g_buf1 : g_buf0) + sIdx * 4096;
    ulonglong2 (*Kp)[8] = KpA + sHalf * 128;
    ulonglong2 (*Vp)[8] = VpA + sHalf * 128;
    u64* Wq2u = (u64*)Wq2; u64* Wk2u = (u64*)Wk2; u64* Wv2u = (u64*)Wv2;

    if (tid < 64) {
        int L = tid >> 5, o = tid & 31;
        gs[L][o] = gga[L * 32 + o];
        bs2[L][o] = bba[L * 32 + o];
    }
    float hrow[32];
#pragma unroll
    for (int o4 = 0; o4 < 8; o4++)
        *(float4*)&hrow[o4 * 4] = *(const float4*)&seq[t * 32 + o4 * 4];

    for (int L = 0; L < 2; L++) {
        __syncthreads();   // prior-layer Wo reads done
        const float* wqL = wq + L * 1024;
        const float* wkL = wk + L * 1024;
        const float* wvL = wv + L * 1024;
        for (int idx = tid; idx < 512; idx += 256) {
            int c = idx >> 4, d = idx & 15;
            Wq2u[c * 16 + d] = pack2(wqL[c * 32 + d], wqL[c * 32 + d + 16]);
            Wk2u[c * 16 + d] = pack2(wkL[c * 32 + d], wkL[c * 32 + d + 16]);
            Wv2u[c * 16 + d] = pack2(wvL[c * 32 + d], wvL[c * 32 + d + 16]);
        }
        __syncthreads();

        u64 qp[16], tv[16];
#pragma unroll
        for (int d = 0; d < 16; d++) qp[d] = 0ULL;
        for (int c = 0; c < 32; c++) {
            u64 hd = pack2(hrow[c], hrow[c]);
#pragma unroll
            for (int j = 0; j < 8; j++) {
                ulonglong2 w = Wq2[c][j];
                qp[2 * j] = fma2(w.x, hd, qp[2 * j]);
                qp[2 * j + 1] = fma2(w.y, hd, qp[2 * j + 1]);
            }
        }
        u64 qsc = pack2(0.25f, 0.25f);   // 1/sqrt(16)
#pragma unroll
        for (int d = 0; d < 16; d++) qp[d] = mul2(qp[d], qsc);

#pragma unroll
        for (int d = 0; d < 16; d++) tv[d] = 0ULL;
        for (int c = 0; c < 32; c++) {
            u64 hd = pack2(hrow[c], hrow[c]);
#pragma unroll
            for (int j = 0; j < 8; j++) {
                ulonglong2 w = Wk2[c][j];
                tv[2 * j] = fma2(w.x, hd, tv[2 * j]);
                tv[2 * j + 1] = fma2(w.y, hd, tv[2 * j + 1]);
            }
        }
#pragma unroll
        for (int j = 0; j < 8; j++)
            Kp[t][j] = make_ulonglong2(tv[2 * j], tv[2 * j + 1]);

#pragma unroll
        for (int d = 0; d < 16; d++) tv[d] = 0ULL;
        for (int c = 0; c < 32; c++) {
            u64 hd = pack2(hrow[c], hrow[c]);
#pragma unroll
            for (int j = 0; j < 8; j++) {
                ulonglong2 w = Wv2[c][j];
                tv[2 * j] = fma2(w.x, hd, tv[2 * j]);
                tv[2 * j + 1] = fma2(w.y, hd, tv[2 * j + 1]);
            }
        }
#pragma unroll
        for (int j = 0; j < 8; j++)
            Vp[t][j] = make_ulonglong2(tv[2 * j], tv[2 * j + 1]);
        __syncthreads();   // all Kp/Vp ready; Wq dead
        const float* woL = wo + L * 1024;
        for (int idx = tid; idx < 512; idx += 256) {
            int c = idx >> 4, d = idx & 15;
            Wq2u[c * 16 + d] = pack2(woL[c * 32 + d], woL[c * 32 + d + 16]);
        }

        // ---- tiled online softmax (8 keys per tile) ----
        float m0 = -3e38f, l0 = 0.f, m1 = -3e38f, l1 = 0.f;
        u64 acc[16];
#pragma unroll
        for (int d = 0; d < 16; d++) acc[d] = 0ULL;
        for (int tile = 0; tile < 16; tile++) {
            float sv0[8], sv1[8];
            float ts0 = -3e38f, ts1 = -3e38f;
#pragma unroll
            for (int q = 0; q < 8; q++) {
                int kp = tile * 8 + q;
                u64 s = 0ULL;
#pragma unroll
                for (int j = 0; j < 8; j++) {
                    ulonglong2 k2 = Kp[kp][j];
                    s = fma2(qp[2 * j], k2.x, s);
                    s = fma2(qp[2 * j + 1], k2.y, s);
                }
                unpack2(s, sv0[q], sv1[q]);
                ts0 = fmaxf(ts0, sv0[q]);
                ts1 = fmaxf(ts1, sv1[q]);
            }
            float nm0 = fmaxf(m0, ts0), nm1 = fmaxf(m1, ts1);
            float cf0 = __expf(m0 - nm0), cf1 = __expf(m1 - nm1);
            l0 *= cf0; l1 *= cf1;
            m0 = nm0; m1 = nm1;
            u64 cfp = pack2(cf0, cf1);
#pragma unroll
            for (int d = 0; d < 16; d++) acc[d] = mul2(acc[d], cfp);
#pragma unroll
            for (int q = 0; q < 8; q++) {
                int kp = tile * 8 + q;
                float p0 = __expf(sv0[q] - m0), p1 = __expf(sv1[q] - m1);
                l0 += p0; l1 += p1;
                u64 pp = pack2(p0, p1);
#pragma unroll
                for (int j = 0; j < 8; j++) {
                    ulonglong2 v2 = Vp[kp][j];
                    acc[2 * j] = fma2(pp, v2.x, acc[2 * j]);
                    acc[2 * j + 1] = fma2(pp, v2.y, acc[2 * j + 1]);
                }
            }
        }
        u64 inv = pack2(1.f / l0, 1.f / l1);
        float ov[32];
#pragma unroll
        for (int d = 0; d < 16; d++) {
            u64 a = mul2(acc[d], inv);
            unpack2(a, ov[d], ov[d + 16]);
        }
        __syncthreads();   // Wo overlay fully visible

        u64 rp[16];
#pragma unroll
        for (int d = 0; d < 16; d++)
            rp[d] = pack2(hrow[d], hrow[d + 16]);   // residual from regs
        for (int c = 0; c < 32; c++) {
            u64 od = pack2(ov[c], ov[c]);
#pragma unroll
            for (int j = 0; j < 8; j++) {
                ulonglong2 w = Wq2[c][j];    // Wo
                rp[2 * j] = fma2(w.x, od, rp[2 * j]);
                rp[2 * j + 1] = fma2(w.y, od, rp[2 * j + 1]);
            }
        }
        float r[32];
#pragma unroll
        for (int d = 0; d < 16; d++) unpack2(rp[d], r[d], r[d + 16]);
        float mu = 0.f;
#pragma unroll
        for (int o = 0; o < 32; o++) mu += r[o];
        mu *= (1.f / 32.f);
        float var = 0.f;
#pragma unroll
        for (int o = 0; o < 32; o++) { float d = r[o] - mu; var += d * d; }
        var *= (1.f / 32.f);
        float rs = rsqrtf(var + 1e-5f);
#pragma unroll
        for (int o = 0; o < 32; o++)
            hrow[o] = (r[o] - mu) * rs * gs[L][o] + bs2[L][o];
    }

    int n = sIdx >> 2, b = sIdx & 3;   // seq chunk = n*B + b
    float* dst = finalOut + ((b * T_ + t) * N_ + n) * D_;
#pragma unroll
    for (int o4 = 0; o4 < 8; o4++)
        *(float4*)&dst[o4 * 4] =
            make_float4(hrow[o4 * 4], hrow[o4 * 4 + 1],
                        hrow[o4 * 4 + 2], hrow[o4 * 4 + 3]);
}

// ---------------- launcher ---------------------------------------------------
extern "C" void kernel_launch(void* const* d_in, const int* in_sizes, int n_in,
                              void* d_out, int out_size) {
    (void)in_sizes; (void)n_in; (void)out_size;
    const float* x   = (const float*)d_in[0];
    const float* E   = (const float*)d_in[2];
    const float* adj = (const float*)d_in[3];
    const float* gw  = (const float*)d_in[4];
    const float* gb  = (const float*)d_in[5];
    const float* tw1 = (const float*)d_in[6];
    const float* tb1 = (const float*)d_in[7];
    const float* tw2 = (const float*)d_in[8];
    const float* tb2 = (const float*)d_in[9];
    const float* awq = (const float*)d_in[10];
    const float* awk = (const float*)d_in[11];
    const float* awv = (const float*)d_in[12];
    const float* awo = (const float*)d_in[13];
    const float* ag  = (const float*)d_in[14];
    const float* ab  = (const float*)d_in[15];
    float* out = (float*)d_out;

    cudaFuncSetAttribute(k_tcn, cudaFuncAttributeMaxDynamicSharedMemorySize,
                         TCN_SMEM);
    cudaFuncSetAttribute(k_aggM, cudaFuncAttributeMaxDynamicSharedMemorySize,
                         AGG_SMEM);
    cudaFuncSetAttribute(k_attn2, cudaFuncAttributeMaxDynamicSharedMemorySize,
                         ATT_SMEM);

    // merged setup: transpose | S2 | wn | adj split in one launch
    k_setup<<<6400, 256>>>(x, adj, E, gw, gb);

    // GCN layer 0: buf0 -> buf1; layer 1: buf1 -> buf0; layer 2: buf0 -> buf1
    k_aggM<<<dim3(128, 8), 256, AGG_SMEM>>>();
    k_combine<<<dim3(N_, 8), 128>>>(0, 0, 1);
    k_aggM<<<dim3(128, 8), 256, AGG_SMEM>>>();
    k_combine<<<dim3(N_, 8), 128>>>(1, 1, 1);
    k_aggM<<<dim3(128, 8), 256, AGG_SMEM>>>();
    k_combine<<<dim3(N_, 8), 128>>>(0, 2, 0);

    // TCN in-place on buf1, 2 sequences per block
    k_tcn<<<N_ * B_ / 2, 128, TCN_SMEM>>>(tw1, tb1, tw2, tb2, 1);

    // merged 2-layer attention, 2 sequences per block; writes final output
    k_attn2<<<N_ * B_ / 2, 256, ATT_SMEM>>>(awq, awk, awv, awo, ag, ab, 1, out);
}